// round 1
// baseline (speedup 1.0000x reference)
#include <cuda_runtime.h>
#include <cstdint>

// Problem constants
#define BB 32
#define II 4096
#define VV 512
#define DD 8

// Tiling
#define VT 256          // v per block
#define IC 32           // i per block (split-K chunk)
#define IG 4            // i per smem stage
#define NCHUNK (II/IC)  // 128
#define NTHREADS 256

// Split-K partial buffer: [chunk][b*V + v]
__device__ float g_part[NCHUNK][BB * VV];

__device__ __forceinline__ void ffma2(unsigned long long& d,
                                      unsigned long long a,
                                      unsigned long long b) {
    asm("fma.rn.f32x2 %0, %1, %2, %0;" : "+l"(d) : "l"(a), "l"(b));
}

// s_partial[chunk][b,v] = sum over i in chunk, d of W[i,v,d]*x[b,i,d]
// Packing: f32x2 lanes = (even-d partial, odd-d partial); summed in epilogue.
__global__ void __launch_bounds__(NTHREADS, 2)
caps_gemm_kernel(const float4* __restrict__ x4, const float4* __restrict__ w4) {
    __shared__ float4 Wsm[IG][2][VT];   // [ig][h][v] = W[i, v, 4h..4h+3]  (32 KB)
    __shared__ float4 Xsm[IG][BB][2];   // [ig][b][h] = x[b, i, 4h..4h+3]  (4 KB)

    const int tid    = threadIdx.x;
    const int v0     = blockIdx.x * VT;
    const int i_base = blockIdx.y * IC;
    const int bg     = tid >> 6;    // 0..3  -> b base = bg*8 (warp-uniform)
    const int vg     = tid & 63;    // 0..63 -> v = v0 + vg + 64*vi

    unsigned long long acc[8][4];
    #pragma unroll
    for (int bi = 0; bi < 8; ++bi)
        #pragma unroll
        for (int vi = 0; vi < 4; ++vi) acc[bi][vi] = 0ull;  // (0.f,0.f)

    for (int s = 0; s < IC / IG; ++s) {
        const int ib = i_base + s * IG;
        __syncthreads();  // protect smem from previous stage's readers
        // ---- stage W: IG rows * 256 v * 8 d = 2048 float4, coalesced ----
        #pragma unroll
        for (int k = 0; k < 8; ++k) {
            int t  = tid + k * NTHREADS;       // 0..2047
            int ig = t >> 9;
            int r  = t & 511;
            int vl = r >> 1;
            int h  = r & 1;
            Wsm[ig][h][vl] =
                w4[(size_t)(ib + ig) * 1024 + (size_t)(v0 + vl) * 2 + h];
        }
        // ---- stage x: IG rows * 32 b * 2 = 256 float4 ----
        {
            int ig = tid >> 6;
            int r  = tid & 63;
            int b  = r >> 1;
            int h  = r & 1;
            Xsm[ig][b][h] = x4[(size_t)b * 8192 + (size_t)(ib + ig) * 2 + h];
        }
        __syncthreads();

        #pragma unroll
        for (int ig = 0; ig < IG; ++ig) {
            #pragma unroll
            for (int h = 0; h < 2; ++h) {
                // W for this thread's 4 v's: conflict-free LDS.128
                ulonglong2 wh[4];
                #pragma unroll
                for (int vi = 0; vi < 4; ++vi)
                    wh[vi] = *(const ulonglong2*)&Wsm[ig][h][vg + 64 * vi];
                #pragma unroll
                for (int half = 0; half < 2; ++half) {
                    // x for 4 b's: warp-uniform broadcast LDS.128
                    ulonglong2 xh[4];
                    #pragma unroll
                    for (int bi = 0; bi < 4; ++bi)
                        xh[bi] = *(const ulonglong2*)
                                     &Xsm[ig][bg * 8 + half * 4 + bi][h];
                    #pragma unroll
                    for (int bi = 0; bi < 4; ++bi)
                        #pragma unroll
                        for (int vi = 0; vi < 4; ++vi) {
                            unsigned long long& a = acc[half * 4 + bi][vi];
                            ffma2(a, xh[bi].x, wh[vi].x);
                            ffma2(a, xh[bi].y, wh[vi].y);
                        }
                }
            }
        }
    }

    // ---- epilogue: lo+hi, store partials (coalesced over vg) ----
    float* outp = &g_part[blockIdx.y][0];
    #pragma unroll
    for (int bi = 0; bi < 8; ++bi)
        #pragma unroll
        for (int vi = 0; vi < 4; ++vi) {
            unsigned long long a = acc[bi][vi];
            float lo = __uint_as_float((unsigned)(a & 0xffffffffull));
            float hi = __uint_as_float((unsigned)(a >> 32));
            outp[(bg * 8 + bi) * VV + v0 + vg + 64 * vi] = lo + hi;
        }
}

// Reduce over chunks, squash, write (t, outputs) — identical halves.
__global__ void __launch_bounds__(256)
caps_finish_kernel(float* __restrict__ out, int out_size) {
    const int b   = blockIdx.x;   // 32 blocks
    const int tid = threadIdx.x;  // 256 threads
    __shared__ float red[256];

    float local[2];
    #pragma unroll
    for (int j = 0; j < 2; ++j) {
        const int v = tid + j * 256;
        float acc = 0.f;
        #pragma unroll 8
        for (int c = 0; c < NCHUNK; ++c) acc += g_part[c][b * VV + v];
        local[j] = acc;
    }

    float sq = local[0] * local[0] + local[1] * local[1];
    red[tid] = sq;
    __syncthreads();
    for (int off = 128; off; off >>= 1) {
        if (tid < off) red[tid] += red[tid + off];
        __syncthreads();
    }
    const float total = red[0];
    const float scale = total / ((1.0f + total) * sqrtf(total));

    #pragma unroll
    for (int j = 0; j < 2; ++j) {
        const int v   = tid + j * 256;
        const float o = local[j] * scale;
        const int idx = b * VV + v;
        if (idx < out_size) out[idx] = o;                       // t
        if (idx + BB * VV < out_size) out[idx + BB * VV] = o;   // outputs
    }
}

extern "C" void kernel_launch(void* const* d_in, const int* in_sizes, int n_in,
                              void* d_out, int out_size) {
    const float4* x4 = (const float4*)d_in[0];  // x: [32, 4096, 8] fp32
    const float4* w4 = (const float4*)d_in[1];  // W: [1, 4096, 512, 8] fp32
    float* out = (float*)d_out;

    dim3 grid1(VV / VT, NCHUNK);  // (2, 128)
    caps_gemm_kernel<<<grid1, NTHREADS>>>(x4, w4);
    caps_finish_kernel<<<BB, 256>>>(out, out_size);
}

// round 2
// speedup vs baseline: 1.0460x; 1.0460x over previous
#include <cuda_runtime.h>
#include <cstdint>

// Problem constants
#define BB 32
#define II 4096
#define VV 512
#define DD 8

// Tiling
#define VT 256          // v per block
#define IC 32           // i per block (split-K chunk)
#define IG 4            // i per pipeline stage
#define NS (IC/IG)      // 8 stages
#define NCHUNK (II/IC)  // 128
#define NRED 8          // second-stage reduction groups
#define NTHREADS 256

// Dynamic smem layout: Wsm[2][IG][2][VT] float4, then Xsm[2][IG][BB][2] float4
#define WSM_F4   (IG * 2 * VT)       // per buffer
#define XSM_F4   (IG * BB * 2)       // per buffer
#define SMEM_F4  (2 * (WSM_F4 + XSM_F4))
#define SMEM_BYTES (SMEM_F4 * 16)    // 73728

__device__ float g_part[NCHUNK][BB * VV];   // split-K partials (8 MB)
__device__ float g_red[NRED][BB * VV];      // second-stage partials (512 KB)

__device__ __forceinline__ void ffma2(unsigned long long& d,
                                      unsigned long long a,
                                      unsigned long long b) {
    asm("fma.rn.f32x2 %0, %1, %2, %0;" : "+l"(d) : "l"(a), "l"(b));
}

__device__ __forceinline__ void cp_async16(float4* smem_dst, const float4* gmem_src) {
    unsigned s = (unsigned)__cvta_generic_to_shared(smem_dst);
    asm volatile("cp.async.cg.shared.global [%0], [%1], 16;"
                 :: "r"(s), "l"(gmem_src));
}
__device__ __forceinline__ void cp_commit() {
    asm volatile("cp.async.commit_group;" ::: "memory");
}
__device__ __forceinline__ void cp_wait1() {
    asm volatile("cp.async.wait_group 1;" ::: "memory");
}
__device__ __forceinline__ void cp_wait0() {
    asm volatile("cp.async.wait_group 0;" ::: "memory");
}

// s_partial[chunk][b,v] = sum over i in chunk, d of W[i,v,d]*x[b,i,d]
// f32x2 lanes = (even-d partial, odd-d partial), summed in epilogue.
__global__ void __launch_bounds__(NTHREADS, 2)
caps_gemm_kernel(const float4* __restrict__ x4, const float4* __restrict__ w4) {
    extern __shared__ float4 dyn[];
    float4 (*Wsm)[IG][2][VT] = (float4(*)[IG][2][VT])dyn;                 // 64 KB
    float4 (*Xsm)[IG][BB][2] = (float4(*)[IG][BB][2])(dyn + 2 * WSM_F4); // 8 KB

    const int tid    = threadIdx.x;
    const int v0     = blockIdx.x * VT;
    const int i_base = blockIdx.y * IC;
    const int bg     = tid >> 6;    // 0..3 -> b base = bg*8 (warp-uniform)
    const int vg     = tid & 63;    // 0..63 -> v = v0 + vg + 64*vi

    // Pre-decoded staging indices (stage-invariant)
    const int wl_ig[8] = { (tid + 0*NTHREADS) >> 9, (tid + 1*NTHREADS) >> 9,
                           (tid + 2*NTHREADS) >> 9, (tid + 3*NTHREADS) >> 9,
                           (tid + 4*NTHREADS) >> 9, (tid + 5*NTHREADS) >> 9,
                           (tid + 6*NTHREADS) >> 9, (tid + 7*NTHREADS) >> 9 };
    const int xs_ig = tid >> 6;
    const int xs_b  = (tid & 63) >> 1;
    const int xs_h  = tid & 1;

    unsigned long long acc[8][4];
    #pragma unroll
    for (int bi = 0; bi < 8; ++bi)
        #pragma unroll
        for (int vi = 0; vi < 4; ++vi) acc[bi][vi] = 0ull;

    // ---- stage loader (cp.async, no register roundtrip) ----
    auto load_stage = [&](int s, int buf) {
        const int ib = i_base + s * IG;
        #pragma unroll
        for (int k = 0; k < 8; ++k) {
            int t  = tid + k * NTHREADS;      // 0..2047
            int ig = wl_ig[k];
            int r  = t & 511;
            int vl = r >> 1;
            int h  = r & 1;
            cp_async16(&Wsm[buf][ig][h][vl],
                       &w4[(size_t)(ib + ig) * 1024 + (size_t)(v0 + vl) * 2 + h]);
        }
        cp_async16(&Xsm[buf][xs_ig][xs_b][xs_h],
                   &x4[(size_t)xs_b * 8192 + (size_t)(ib + xs_ig) * 2 + xs_h]);
    };

    load_stage(0, 0);
    cp_commit();

    for (int s = 0; s < NS; ++s) {
        const int buf = s & 1;
        if (s + 1 < NS) {            // prefetch next into other buffer
            load_stage(s + 1, buf ^ 1);
            cp_commit();
            cp_wait1();              // stage s resident
        } else {
            cp_wait0();
        }
        __syncthreads();

        #pragma unroll
        for (int ig = 0; ig < IG; ++ig) {
            #pragma unroll
            for (int h = 0; h < 2; ++h) {
                ulonglong2 wh[4];   // 4 v's, conflict-free LDS.128
                #pragma unroll
                for (int vi = 0; vi < 4; ++vi)
                    wh[vi] = *(const ulonglong2*)&Wsm[buf][ig][h][vg + 64 * vi];
                #pragma unroll
                for (int half = 0; half < 2; ++half) {
                    ulonglong2 xh[4];  // broadcast LDS.128
                    #pragma unroll
                    for (int bi = 0; bi < 4; ++bi)
                        xh[bi] = *(const ulonglong2*)
                                     &Xsm[buf][ig][bg * 8 + half * 4 + bi][h];
                    #pragma unroll
                    for (int bi = 0; bi < 4; ++bi)
                        #pragma unroll
                        for (int vi = 0; vi < 4; ++vi) {
                            unsigned long long& a = acc[half * 4 + bi][vi];
                            ffma2(a, xh[bi].x, wh[vi].x);
                            ffma2(a, xh[bi].y, wh[vi].y);
                        }
                }
            }
        }
        __syncthreads();   // all warps done with buf before it is re-loaded
    }

    // ---- epilogue: lo+hi, store partials (coalesced over vg) ----
    float* outp = &g_part[blockIdx.y][0];
    #pragma unroll
    for (int bi = 0; bi < 8; ++bi)
        #pragma unroll
        for (int vi = 0; vi < 4; ++vi) {
            unsigned long long a = acc[bi][vi];
            float lo = __uint_as_float((unsigned)(a & 0xffffffffull));
            float hi = __uint_as_float((unsigned)(a >> 32));
            outp[(bg * 8 + bi) * VV + v0 + vg + 64 * vi] = lo + hi;
        }
}

// First-stage reduction: 256 blocks, each folds 16 chunks for one b.
__global__ void __launch_bounds__(256)
caps_reduce_kernel() {
    const int b   = blockIdx.x;   // 0..31
    const int s   = blockIdx.y;   // 0..7
    const int tid = threadIdx.x;
    #pragma unroll
    for (int j = 0; j < 2; ++j) {
        const int v = tid + j * 256;
        float acc = 0.f;
        #pragma unroll
        for (int c = 0; c < NCHUNK / NRED; ++c)
            acc += g_part[s * (NCHUNK / NRED) + c][b * VV + v];
        g_red[s][b * VV + v] = acc;
    }
}

// Final: fold 8 partials, squash, write (t, outputs) — identical halves.
__global__ void __launch_bounds__(256)
caps_finish_kernel(float* __restrict__ out, int out_size) {
    const int b   = blockIdx.x;   // 32 blocks
    const int tid = threadIdx.x;  // 256 threads
    __shared__ float red[256];

    float local[2];
    #pragma unroll
    for (int j = 0; j < 2; ++j) {
        const int v = tid + j * 256;
        float acc = 0.f;
        #pragma unroll
        for (int c = 0; c < NRED; ++c) acc += g_red[c][b * VV + v];
        local[j] = acc;
    }

    float sq = local[0] * local[0] + local[1] * local[1];
    red[tid] = sq;
    __syncthreads();
    for (int off = 128; off; off >>= 1) {
        if (tid < off) red[tid] += red[tid + off];
        __syncthreads();
    }
    const float total = red[0];
    const float scale = total / ((1.0f + total) * sqrtf(total));

    #pragma unroll
    for (int j = 0; j < 2; ++j) {
        const int v   = tid + j * 256;
        const float o = local[j] * scale;
        const int idx = b * VV + v;
        if (idx < out_size) out[idx] = o;                       // t
        if (idx + BB * VV < out_size) out[idx + BB * VV] = o;   // outputs
    }
}

extern "C" void kernel_launch(void* const* d_in, const int* in_sizes, int n_in,
                              void* d_out, int out_size) {
    const float4* x4 = (const float4*)d_in[0];  // x: [32, 4096, 8] fp32
    const float4* w4 = (const float4*)d_in[1];  // W: [1, 4096, 512, 8] fp32
    float* out = (float*)d_out;

    static bool attr_set = false;
    if (!attr_set) {
        cudaFuncSetAttribute(caps_gemm_kernel,
                             cudaFuncAttributeMaxDynamicSharedMemorySize,
                             SMEM_BYTES);
        attr_set = true;
    }

    dim3 grid1(VV / VT, NCHUNK);  // (2, 128)
    caps_gemm_kernel<<<grid1, NTHREADS, SMEM_BYTES>>>(x4, w4);
    caps_reduce_kernel<<<dim3(BB, NRED), 256>>>();
    caps_finish_kernel<<<BB, 256>>>(out, out_size);
}